// round 1
// baseline (speedup 1.0000x reference)
#include <cuda_runtime.h>
#include <cstdint>

#define NBATCH 32
#define HDIM 56
#define WDIM 56
#define CIN 128
#define OUTC 128
#define NGRP 8
#define HC 64
#define BNC 0.9995003747f   // 1/sqrt(1+1e-3)
#define SPITCH 3137         // 56*56 + 1 (bank-skew pad)

// Scratch buffers for q/k/v (post-BN). __device__ globals per allocation rules.
__device__ float g_qbuf[(size_t)NBATCH*HDIM*WDIM*HC];
__device__ float g_kbuf[(size_t)NBATCH*HDIM*WDIM*HC];
__device__ float g_vbuf[(size_t)NBATCH*HDIM*WDIM*OUTC];

typedef unsigned long long u64;

__device__ __forceinline__ u64 pk2(float lo, float hi){
    u64 r;
    asm("mov.b64 %0, {%1, %2};" : "=l"(r) : "r"(__float_as_uint(lo)), "r"(__float_as_uint(hi)));
    return r;
}
__device__ __forceinline__ float2 upk2(u64 v){
    unsigned lo, hi;
    asm("mov.b64 {%0, %1}, %2;" : "=r"(lo), "=r"(hi) : "l"(v));
    return make_float2(__uint_as_float(lo), __uint_as_float(hi));
}
__device__ __forceinline__ u64 ffma2(u64 a, u64 b, u64 c){
    u64 d; asm("fma.rn.f32x2 %0, %1, %2, %3;" : "=l"(d) : "l"(a), "l"(b), "l"(c)); return d;
}
__device__ __forceinline__ u64 fmul2(u64 a, u64 b){
    u64 d; asm("mul.rn.f32x2 %0, %1, %2;" : "=l"(d) : "l"(a), "l"(b)); return d;
}
__device__ __forceinline__ float hadd2(u64 v){ float2 f = upk2(v); return f.x + f.y; }

// ---------------------------------------------------------------------------
// Kernel A: fused Q/K/V 1x1-conv GEMM + BN.
// M = N*H*W = 100352 rows, K = 128, 256 output cols split over blockIdx.y:
//   cb 0 -> q (64 ch), cb 1 -> k (64 ch), cb 2/3 -> v (2 x 64 ch).
// Tile: 64 rows x 64 cols, 128 threads, each thread 8x4 outputs via f32x2.
// ---------------------------------------------------------------------------
__global__ __launch_bounds__(128) void qkv_kernel(
    const float* __restrict__ x,
    const float* __restrict__ wq, const float* __restrict__ wk, const float* __restrict__ wv,
    const float* __restrict__ gq, const float* __restrict__ bq,
    const float* __restrict__ gk, const float* __restrict__ bk,
    const float* __restrict__ gv, const float* __restrict__ bv)
{
    __shared__ float Xs[64][17];
    __shared__ float Ws[16][64];
    const int tid = threadIdx.x;
    const int tx = tid & 15;    // col group (4 cols)
    const int ty = tid >> 4;    // row group (8 rows)
    const int row0 = blockIdx.x * 64;
    const int cb = blockIdx.y;

    const float* wsrc; int wld, wcol0; float* dst; int dld, dcol0;
    const float* gam; const float* bet; int ch0;
    if (cb == 0){ wsrc=wq; wld=HC;   wcol0=0; dst=g_qbuf; dld=HC;   dcol0=0; gam=gq; bet=bq; ch0=0; }
    else if (cb == 1){ wsrc=wk; wld=HC; wcol0=0; dst=g_kbuf; dld=HC; dcol0=0; gam=gk; bet=bk; ch0=0; }
    else { int h=(cb-2)*64; wsrc=wv; wld=OUTC; wcol0=h; dst=g_vbuf; dld=OUTC; dcol0=h; gam=gv; bet=bv; ch0=h; }

    u64 acc[8][2];
    #pragma unroll
    for (int j=0;j<8;j++){ acc[j][0]=0ULL; acc[j][1]=0ULL; }

    for (int kk=0; kk<8; kk++){
        #pragma unroll
        for (int l=0;l<8;l++){
            int idx = tid + l*128;
            int r = idx >> 4, c = idx & 15;
            Xs[r][c] = x[(size_t)(row0 + r)*CIN + kk*16 + c];
        }
        #pragma unroll
        for (int l=0;l<8;l++){
            int idx = tid + l*128;
            int r = idx >> 6, c = idx & 63;
            Ws[r][c] = wsrc[(size_t)(kk*16 + r)*wld + wcol0 + c];
        }
        __syncthreads();
        #pragma unroll
        for (int k=0;k<16;k++){
            float4 b4 = *(const float4*)&Ws[k][tx*4];
            u64 b01 = pk2(b4.x, b4.y);
            u64 b23 = pk2(b4.z, b4.w);
            #pragma unroll
            for (int j=0;j<8;j++){
                float a = Xs[ty*8 + j][k];
                u64 ap = pk2(a, a);
                acc[j][0] = ffma2(ap, b01, acc[j][0]);
                acc[j][1] = ffma2(ap, b23, acc[j][1]);
            }
        }
        __syncthreads();
    }
    float sc[4], bb[4];
    #pragma unroll
    for (int c=0;c<4;c++){
        int ch = ch0 + tx*4 + c;
        sc[c] = gam[ch]*BNC;
        bb[c] = bet[ch];
    }
    #pragma unroll
    for (int j=0;j<8;j++){
        float2 f0 = upk2(acc[j][0]);
        float2 f1 = upk2(acc[j][1]);
        float4 o;
        o.x = f0.x*sc[0]+bb[0]; o.y = f0.y*sc[1]+bb[1];
        o.z = f1.x*sc[2]+bb[2]; o.w = f1.y*sc[3]+bb[3];
        *(float4*)&dst[(size_t)(row0 + ty*8 + j)*dld + dcol0 + tx*4] = o;
    }
}

// ---------------------------------------------------------------------------
// Kernel B: fused axial attention. One block per (g, b), 448 threads.
// K-slice [56j][56w][8c] staged in smem; i processed in 7 tiles of 8 with the
// logits tile S[8][56j][56w] in smem (softmax over w is block-local).
// V streamed from L2 with ti-lanes packed so same-(j,w) lines dedup in-warp.
// ---------------------------------------------------------------------------
__global__ __launch_bounds__(448) void attn_kernel(
    const float* __restrict__ qrel, const float* __restrict__ krel, const float* __restrict__ vrel,
    const float* __restrict__ gqk, const float* __restrict__ bqk,
    const float* __restrict__ gqr, const float* __restrict__ bqr,
    const float* __restrict__ gkr, const float* __restrict__ bkr,
    const float* __restrict__ gsv, const float* __restrict__ bsv,
    const float* __restrict__ gsve, const float* __restrict__ bsve,
    float* __restrict__ out)
{
    extern __shared__ float sm[];
    float* Ssh = sm;                 // 8*3137  = 25096 floats
    float* Ksh = sm + 8*SPITCH;      // 56*56*8 = 25088
    float* QR  = Ksh + 25088;        // 111*8   = 888
    float* KR  = QR + 888;           // 888
    float* VR  = KR + 888;           // 111*16  = 1776

    const int g = blockIdx.x;
    const int b = blockIdx.y;
    const int tid = threadIdx.x;

    const float sqk = gqk[g]*BNC, sqr = gqr[g]*BNC, skr = gkr[g]*BNC;
    const float cbias = bqk[g] + bqr[g] + bkr[g];  // constant over w: softmax-neutral but kept

    // stage K slice + relative tables
    for (int idx = tid; idx < 6272; idx += 448){
        int j = idx / 112;
        int r = idx - j*112;
        int w = r >> 1, qq = r & 1;
        float4 v = *(const float4*)&g_kbuf[((size_t)(b*HDIM + j)*WDIM + w)*HC + g*8 + qq*4];
        *(float4*)&Ksh[(j*56 + w)*8 + qq*4] = v;
    }
    for (int idx = tid; idx < 888; idx += 448){ QR[idx] = qrel[idx]; KR[idx] = krel[idx]; }
    for (int idx = tid; idx < 1776; idx += 448) VR[idx] = vrel[idx];
    __syncthreads();

    for (int it = 0; it < 7; it++){
        const int i0 = it*8;
        // ---- phase A: logits S[ti][j][w] ----
        for (int e = tid; e < 25088; e += 448){
            int ti = e / 3136;
            int r  = e - ti*3136;
            int j  = r / 56;
            int w  = r - j*56;
            int i  = i0 + ti;
            const float* qp = &g_qbuf[((size_t)(b*HDIM + i)*WDIM + w)*HC + g*8];
            float4 q0 = *(const float4*)qp;
            float4 q1 = *(const float4*)(qp+4);
            const float* kp = &Ksh[(j*56 + w)*8];
            float4 k0 = *(const float4*)kp;
            float4 k1 = *(const float4*)(kp+4);
            const float* rp = &QR[(i - j + 55)*8];
            float4 r0 = *(const float4*)rp;
            float4 r1 = *(const float4*)(rp+4);
            const float* cp = &KR[(j - i + 55)*8];
            float4 c0 = *(const float4*)cp;
            float4 c1 = *(const float4*)(cp+4);

            u64 qa = pk2(q0.x,q0.y), qb2 = pk2(q0.z,q0.w), qc = pk2(q1.x,q1.y), qd = pk2(q1.z,q1.w);
            u64 ka = pk2(k0.x,k0.y), kb2 = pk2(k0.z,k0.w), kc = pk2(k1.x,k1.y), kd = pk2(k1.z,k1.w);
            u64 ra = pk2(r0.x,r0.y), rb2 = pk2(r0.z,r0.w), rc = pk2(r1.x,r1.y), rd = pk2(r1.z,r1.w);
            u64 ca = pk2(c0.x,c0.y), cb2 = pk2(c0.z,c0.w), cc2 = pk2(c1.x,c1.y), cd = pk2(c1.z,c1.w);

            u64 dqk = fmul2(qa,ka); dqk = ffma2(qb2,kb2,dqk); dqk = ffma2(qc,kc,dqk); dqk = ffma2(qd,kd,dqk);
            u64 dqr = fmul2(qa,ra); dqr = ffma2(qb2,rb2,dqr); dqr = ffma2(qc,rc,dqr); dqr = ffma2(qd,rd,dqr);
            u64 dkr = fmul2(ka,ca); dkr = ffma2(kb2,cb2,dkr); dkr = ffma2(kc,cc2,dkr); dkr = ffma2(kd,cd,dkr);

            float S = hadd2(dqk)*sqk + hadd2(dqr)*sqr + hadd2(dkr)*skr + cbias;
            Ssh[ti*SPITCH + j*56 + w] = S;
        }
        __syncthreads();
        // ---- phase B: softmax over w for each (ti, j) row ----
        {
            int ti = tid & 7, j = tid >> 3;   // 448 = 8*56 rows exactly
            float* row = &Ssh[ti*SPITCH + j*56];
            float m = row[0];
            #pragma unroll 8
            for (int w=1; w<56; w++) m = fmaxf(m, row[w]);
            float s = 0.f;
            #pragma unroll 8
            for (int w=0; w<56; w++){ float e = __expf(row[w]-m); row[w] = e; s += e; }
            float inv = 1.0f/s;
            #pragma unroll 8
            for (int w=0; w<56; w++) row[w] *= inv;
        }
        __syncthreads();
        // ---- phase C: sv + sve contraction over j, BN epilogue, store ----
        {
            int ti = tid & 7, w = tid >> 3;   // ti fastest: 8 lanes share each v line
            int i = i0 + ti;
            u64 sv[8], se[8];
            #pragma unroll
            for (int p=0;p<8;p++){ sv[p]=0ULL; se[p]=0ULL; }
            const float* vbase = &g_vbuf[((size_t)(b*HDIM)*WDIM + w)*OUTC + g*16];
            const float* Sb = &Ssh[ti*SPITCH + w];
            for (int j=0;j<56;j++){
                float s = Sb[j*56];
                u64 sp = pk2(s,s);
                const float* vp = vbase + (size_t)j*(WDIM*OUTC);
                float4 v0 = *(const float4*)(vp);
                float4 v1 = *(const float4*)(vp+4);
                float4 v2 = *(const float4*)(vp+8);
                float4 v3 = *(const float4*)(vp+12);
                const float* ep = &VR[(j - i + 55)*16];
                float4 e0 = *(const float4*)(ep);
                float4 e1 = *(const float4*)(ep+4);
                float4 e2 = *(const float4*)(ep+8);
                float4 e3 = *(const float4*)(ep+12);
                sv[0]=ffma2(sp, pk2(v0.x,v0.y), sv[0]);
                sv[1]=ffma2(sp, pk2(v0.z,v0.w), sv[1]);
                sv[2]=ffma2(sp, pk2(v1.x,v1.y), sv[2]);
                sv[3]=ffma2(sp, pk2(v1.z,v1.w), sv[3]);
                sv[4]=ffma2(sp, pk2(v2.x,v2.y), sv[4]);
                sv[5]=ffma2(sp, pk2(v2.z,v2.w), sv[5]);
                sv[6]=ffma2(sp, pk2(v3.x,v3.y), sv[6]);
                sv[7]=ffma2(sp, pk2(v3.z,v3.w), sv[7]);
                se[0]=ffma2(sp, pk2(e0.x,e0.y), se[0]);
                se[1]=ffma2(sp, pk2(e0.z,e0.w), se[1]);
                se[2]=ffma2(sp, pk2(e1.x,e1.y), se[2]);
                se[3]=ffma2(sp, pk2(e1.z,e1.w), se[3]);
                se[4]=ffma2(sp, pk2(e2.x,e2.y), se[4]);
                se[5]=ffma2(sp, pk2(e2.z,e2.w), se[5]);
                se[6]=ffma2(sp, pk2(e3.x,e3.y), se[6]);
                se[7]=ffma2(sp, pk2(e3.z,e3.w), se[7]);
            }
            float* op = &out[((size_t)(b*HDIM + i)*WDIM + w)*OUTC + g*16];
            #pragma unroll
            for (int p=0;p<4;p++){
                float2 a0 = upk2(sv[2*p]);
                float2 a1 = upk2(sv[2*p+1]);
                float2 b0 = upk2(se[2*p]);
                float2 b1 = upk2(se[2*p+1]);
                int ch = g*16 + p*4;
                float4 o;
                o.x = a0.x*gsv[ch+0]*BNC + bsv[ch+0] + b0.x*gsve[ch+0]*BNC + bsve[ch+0];
                o.y = a0.y*gsv[ch+1]*BNC + bsv[ch+1] + b0.y*gsve[ch+1]*BNC + bsve[ch+1];
                o.z = a1.x*gsv[ch+2]*BNC + bsv[ch+2] + b1.x*gsve[ch+2]*BNC + bsve[ch+2];
                o.w = a1.y*gsv[ch+3]*BNC + bsv[ch+3] + b1.y*gsve[ch+3]*BNC + bsve[ch+3];
                *(float4*)(op + p*4) = o;
            }
        }
        __syncthreads();   // Ssh reused next i-tile
    }
}

extern "C" void kernel_launch(void* const* d_in, const int* in_sizes, int n_in,
                              void* d_out, int out_size)
{
    (void)in_sizes; (void)n_in; (void)out_size;
    const float* x    = (const float*)d_in[0];
    const float* wq   = (const float*)d_in[1];
    const float* wk   = (const float*)d_in[2];
    const float* wv   = (const float*)d_in[3];
    const float* qrel = (const float*)d_in[4];
    const float* krel = (const float*)d_in[5];
    const float* vrel = (const float*)d_in[6];
    const float* gq = (const float*)d_in[7];   const float* bq = (const float*)d_in[8];
    const float* gk = (const float*)d_in[9];   const float* bk = (const float*)d_in[10];
    const float* gv = (const float*)d_in[11];  const float* bv = (const float*)d_in[12];
    const float* gqk= (const float*)d_in[13];  const float* bqk= (const float*)d_in[14];
    const float* gqr= (const float*)d_in[15];  const float* bqr= (const float*)d_in[16];
    const float* gkr= (const float*)d_in[17];  const float* bkr= (const float*)d_in[18];
    const float* gsv= (const float*)d_in[19];  const float* bsv= (const float*)d_in[20];
    const float* gsve=(const float*)d_in[21];  const float* bsve=(const float*)d_in[22];
    float* out = (float*)d_out;

    const int smem_bytes = (8*SPITCH + 25088 + 888 + 888 + 1776) * (int)sizeof(float); // 214944
    cudaFuncSetAttribute(attn_kernel, cudaFuncAttributeMaxDynamicSharedMemorySize, smem_bytes);

    qkv_kernel<<<dim3(1568, 4), 128>>>(x, wq, wk, wv, gq, bq, gk, bk, gv, bv);
    attn_kernel<<<dim3(NGRP, NBATCH), 448, smem_bytes>>>(
        qrel, krel, vrel, gqk, bqk, gqr, bqr, gkr, bkr, gsv, bsv, gsve, bsve, out);
}

// round 3
// speedup vs baseline: 1.4849x; 1.4849x over previous
#include <cuda_runtime.h>
#include <cstdint>

#define NBATCH 32
#define HDIM 56
#define WDIM 56
#define CIN 128
#define OUTC 128
#define NGRP 8
#define HC 64
#define BNC 0.9995003747f   // 1/sqrt(1+1e-3)
#define SPITCH 3140         // 56*56 rounded up to mult of 4 (+bank skew 4)

// Scratch buffers for q/k/v (post-BN). __device__ globals per allocation rules.
__device__ float g_qbuf[(size_t)NBATCH*HDIM*WDIM*HC];
__device__ float g_kbuf[(size_t)NBATCH*HDIM*WDIM*HC];
__device__ float g_vbuf[(size_t)NBATCH*HDIM*WDIM*OUTC];

typedef unsigned long long u64;

__device__ __forceinline__ u64 pk2(float lo, float hi){
    u64 r;
    asm("mov.b64 %0, {%1, %2};" : "=l"(r) : "r"(__float_as_uint(lo)), "r"(__float_as_uint(hi)));
    return r;
}
__device__ __forceinline__ float2 upk2(u64 v){
    unsigned lo, hi;
    asm("mov.b64 {%0, %1}, %2;" : "=r"(lo), "=r"(hi) : "l"(v));
    return make_float2(__uint_as_float(lo), __uint_as_float(hi));
}
__device__ __forceinline__ u64 ffma2(u64 a, u64 b, u64 c){
    u64 d; asm("fma.rn.f32x2 %0, %1, %2, %3;" : "=l"(d) : "l"(a), "l"(b), "l"(c)); return d;
}
__device__ __forceinline__ u64 fmul2(u64 a, u64 b){
    u64 d; asm("mul.rn.f32x2 %0, %1, %2;" : "=l"(d) : "l"(a), "l"(b)); return d;
}
__device__ __forceinline__ float hadd2(u64 v){ float2 f = upk2(v); return f.x + f.y; }

// ---------------------------------------------------------------------------
// Kernel A: fused Q/K/V 1x1-conv GEMM + BN. (unchanged this round)
// ---------------------------------------------------------------------------
__global__ __launch_bounds__(128) void qkv_kernel(
    const float* __restrict__ x,
    const float* __restrict__ wq, const float* __restrict__ wk, const float* __restrict__ wv,
    const float* __restrict__ gq, const float* __restrict__ bq,
    const float* __restrict__ gk, const float* __restrict__ bk,
    const float* __restrict__ gv, const float* __restrict__ bv)
{
    __shared__ float Xs[64][17];
    __shared__ float Ws[16][64];
    const int tid = threadIdx.x;
    const int tx = tid & 15;
    const int ty = tid >> 4;
    const int row0 = blockIdx.x * 64;
    const int cb = blockIdx.y;

    const float* wsrc; int wld, wcol0; float* dst; int dld, dcol0;
    const float* gam; const float* bet; int ch0;
    if (cb == 0){ wsrc=wq; wld=HC;   wcol0=0; dst=g_qbuf; dld=HC;   dcol0=0; gam=gq; bet=bq; ch0=0; }
    else if (cb == 1){ wsrc=wk; wld=HC; wcol0=0; dst=g_kbuf; dld=HC; dcol0=0; gam=gk; bet=bk; ch0=0; }
    else { int h=(cb-2)*64; wsrc=wv; wld=OUTC; wcol0=h; dst=g_vbuf; dld=OUTC; dcol0=h; gam=gv; bet=bv; ch0=h; }

    u64 acc[8][2];
    #pragma unroll
    for (int j=0;j<8;j++){ acc[j][0]=0ULL; acc[j][1]=0ULL; }

    for (int kk=0; kk<8; kk++){
        #pragma unroll
        for (int l=0;l<8;l++){
            int idx = tid + l*128;
            int r = idx >> 4, c = idx & 15;
            Xs[r][c] = x[(size_t)(row0 + r)*CIN + kk*16 + c];
        }
        #pragma unroll
        for (int l=0;l<8;l++){
            int idx = tid + l*128;
            int r = idx >> 6, c = idx & 63;
            Ws[r][c] = wsrc[(size_t)(kk*16 + r)*wld + wcol0 + c];
        }
        __syncthreads();
        #pragma unroll
        for (int k=0;k<16;k++){
            float4 b4 = *(const float4*)&Ws[k][tx*4];
            u64 b01 = pk2(b4.x, b4.y);
            u64 b23 = pk2(b4.z, b4.w);
            #pragma unroll
            for (int j=0;j<8;j++){
                float a = Xs[ty*8 + j][k];
                u64 ap = pk2(a, a);
                acc[j][0] = ffma2(ap, b01, acc[j][0]);
                acc[j][1] = ffma2(ap, b23, acc[j][1]);
            }
        }
        __syncthreads();
    }
    float sc[4], bb[4];
    #pragma unroll
    for (int c=0;c<4;c++){
        int ch = ch0 + tx*4 + c;
        sc[c] = gam[ch]*BNC;
        bb[c] = bet[ch];
    }
    #pragma unroll
    for (int j=0;j<8;j++){
        float2 f0 = upk2(acc[j][0]);
        float2 f1 = upk2(acc[j][1]);
        float4 o;
        o.x = f0.x*sc[0]+bb[0]; o.y = f0.y*sc[1]+bb[1];
        o.z = f1.x*sc[2]+bb[2]; o.w = f1.y*sc[3]+bb[3];
        *(float4*)&dst[(size_t)(row0 + ty*8 + j)*dld + dcol0 + tx*4] = o;
    }
}

// ---------------------------------------------------------------------------
// Kernel B v2: axial attention. One block per (it, g, b): 1792 blocks,
// 448 threads, 2 blocks/SM (112 KB smem). Thread = (ti, w); ti is the fast
// lane index so k/VR/QR/KR accesses dedup inside the warp. No K staging —
// warp coalescing provides the same dedup as smem did. q lives in registers.
// Softmax over w is block-local in Ssh; 2 passes + inv folded into phase C.
// ---------------------------------------------------------------------------
__global__ __launch_bounds__(448, 2) void attn_kernel(
    const float* __restrict__ qrel, const float* __restrict__ krel, const float* __restrict__ vrel,
    const float* __restrict__ gqk, const float* __restrict__ bqk,
    const float* __restrict__ gqr, const float* __restrict__ bqr,
    const float* __restrict__ gkr, const float* __restrict__ bkr,
    const float* __restrict__ gsv, const float* __restrict__ bsv,
    const float* __restrict__ gsve, const float* __restrict__ bsve,
    float* __restrict__ out)
{
    extern __shared__ float sm[];
    float* Ssh = sm;                 // 8*3140 = 25120 floats
    float* QR  = sm + 8*SPITCH;      // 888 (dead after phase A; aliased as Inv)
    float* KR  = QR + 888;           // 888
    float* VR  = KR + 888;           // 1776
    float* Inv = QR;                 // 448 floats, written in phase B

    const int it = blockIdx.x;
    const int g  = blockIdx.y;
    const int b  = blockIdx.z;
    const int tid = threadIdx.x;
    const int ti = tid & 7;          // fast: 8 lanes share k/VR rows
    const int w  = tid >> 3;         // 0..55
    const int i  = it*8 + ti;

    const float sqk = gqk[g]*BNC, sqr = gqr[g]*BNC, skr = gkr[g]*BNC;
    const float cbias = bqk[g] + bqr[g] + bkr[g];

    for (int idx = tid; idx < 888; idx += 448){ QR[idx] = qrel[idx]; KR[idx] = krel[idx]; }
    for (int idx = tid; idx < 1776; idx += 448) VR[idx] = vrel[idx];
    __syncthreads();

    // ---- phase A: S[ti][j][w] for this i-tile ----
    {
        const float* qp = &g_qbuf[((size_t)(b*HDIM + i)*WDIM + w)*HC + g*8];
        float4 q0 = *(const float4*)qp;
        float4 q1 = *(const float4*)(qp+4);
        u64 qa = pk2(q0.x,q0.y), qb2 = pk2(q0.z,q0.w), qc = pk2(q1.x,q1.y), qd = pk2(q1.z,q1.w);

        const float* kbase = &g_kbuf[((size_t)(b*HDIM)*WDIM + w)*HC + g*8];
        float* srow = &Ssh[ti*SPITCH + w];

        #pragma unroll 2
        for (int j = 0; j < 56; j++){
            const float* kp = kbase + (size_t)j*(WDIM*HC);
            float4 k0 = *(const float4*)kp;
            float4 k1 = *(const float4*)(kp+4);
            const float* rp = &QR[(i - j + 55)*8];
            float4 r0 = *(const float4*)rp;
            float4 r1 = *(const float4*)(rp+4);
            const float* cp = &KR[(j - i + 55)*8];
            float4 c0 = *(const float4*)cp;
            float4 c1 = *(const float4*)(cp+4);

            u64 ka = pk2(k0.x,k0.y), kb2 = pk2(k0.z,k0.w), kc = pk2(k1.x,k1.y), kd = pk2(k1.z,k1.w);
            u64 ra = pk2(r0.x,r0.y), rb2 = pk2(r0.z,r0.w), rc = pk2(r1.x,r1.y), rd = pk2(r1.z,r1.w);
            u64 ca = pk2(c0.x,c0.y), cb2 = pk2(c0.z,c0.w), cc2 = pk2(c1.x,c1.y), cd = pk2(c1.z,c1.w);

            u64 dqk = fmul2(qa,ka); dqk = ffma2(qb2,kb2,dqk); dqk = ffma2(qc,kc,dqk); dqk = ffma2(qd,kd,dqk);
            u64 dqr = fmul2(qa,ra); dqr = ffma2(qb2,rb2,dqr); dqr = ffma2(qc,rc,dqr); dqr = ffma2(qd,rd,dqr);
            u64 dkr = fmul2(ka,ca); dkr = ffma2(kb2,cb2,dkr); dkr = ffma2(kc,cc2,dkr); dkr = ffma2(kd,cd,dkr);

            srow[j*56] = hadd2(dqk)*sqk + hadd2(dqr)*sqr + hadd2(dkr)*skr + cbias;
        }
    }
    __syncthreads();

    // ---- phase B: softmax over w for each (ti, j) row; store e and 1/sum ----
    {
        const int bti = tid & 7, bj = tid >> 3;          // 448 rows, 1 thread each
        float4* row = (float4*)&Ssh[bti*SPITCH + bj*56];
        float m = -3.4e38f;
        #pragma unroll
        for (int p = 0; p < 14; p++){
            float4 t = row[p];
            m = fmaxf(m, fmaxf(fmaxf(t.x, t.y), fmaxf(t.z, t.w)));
        }
        float s = 0.f;
        #pragma unroll
        for (int p = 0; p < 14; p++){
            float4 t = row[p];
            t.x = __expf(t.x - m); t.y = __expf(t.y - m);
            t.z = __expf(t.z - m); t.w = __expf(t.w - m);
            s += (t.x + t.y) + (t.z + t.w);
            row[p] = t;
        }
        Inv[tid] = 1.0f / s;      // index = bj*8 + bti == tid
    }
    __syncthreads();

    // ---- phase C: sv + sve contraction over j, BN epilogue, store ----
    {
        u64 sv[8], se[8];
        #pragma unroll
        for (int p=0;p<8;p++){ sv[p]=0ULL; se[p]=0ULL; }
        const float* vbase = &g_vbuf[((size_t)(b*HDIM)*WDIM + w)*OUTC + g*16];
        const float* Sb = &Ssh[ti*SPITCH + w];
        const float* eb = &VR[(55 - i)*16];
        const float* ib = &Inv[ti];

        #pragma unroll 2
        for (int j = 0; j < 56; j++){
            float s = Sb[j*56] * ib[j*8];
            u64 sp = pk2(s, s);
            const float* vp = vbase + (size_t)j*(WDIM*OUTC);
            float4 v0 = *(const float4*)(vp);
            float4 v1 = *(const float4*)(vp+4);
            float4 v2 = *(const float4*)(vp+8);
            float4 v3 = *(const float4*)(vp+12);
            const float* ep = eb + j*16;
            float4 e0 = *(const float4*)(ep);
            float4 e1 = *(const float4*)(ep+4);
            float4 e2 = *(const float4*)(ep+8);
            float4 e3 = *(const float4*)(ep+12);
            sv[0]=ffma2(sp, pk2(v0.x,v0.y), sv[0]);
            sv[1]=ffma2(sp, pk2(v0.z,v0.w), sv[1]);
            sv[2]=ffma2(sp, pk2(v1.x,v1.y), sv[2]);
            sv[3]=ffma2(sp, pk2(v1.z,v1.w), sv[3]);
            sv[4]=ffma2(sp, pk2(v2.x,v2.y), sv[4]);
            sv[5]=ffma2(sp, pk2(v2.z,v2.w), sv[5]);
            sv[6]=ffma2(sp, pk2(v3.x,v3.y), sv[6]);
            sv[7]=ffma2(sp, pk2(v3.z,v3.w), sv[7]);
            se[0]=ffma2(sp, pk2(e0.x,e0.y), se[0]);
            se[1]=ffma2(sp, pk2(e0.z,e0.w), se[1]);
            se[2]=ffma2(sp, pk2(e1.x,e1.y), se[2]);
            se[3]=ffma2(sp, pk2(e1.z,e1.w), se[3]);
            se[4]=ffma2(sp, pk2(e2.x,e2.y), se[4]);
            se[5]=ffma2(sp, pk2(e2.z,e2.w), se[5]);
            se[6]=ffma2(sp, pk2(e3.x,e3.y), se[6]);
            se[7]=ffma2(sp, pk2(e3.z,e3.w), se[7]);
        }
        float* op = &out[((size_t)(b*HDIM + i)*WDIM + w)*OUTC + g*16];
        #pragma unroll
        for (int p=0;p<4;p++){
            float2 a0 = upk2(sv[2*p]);
            float2 a1 = upk2(sv[2*p+1]);
            float2 b0 = upk2(se[2*p]);
            float2 b1 = upk2(se[2*p+1]);
            int ch = g*16 + p*4;
            float4 o;
            o.x = a0.x*gsv[ch+0]*BNC + bsv[ch+0] + b0.x*gsve[ch+0]*BNC + bsve[ch+0];
            o.y = a0.y*gsv[ch+1]*BNC + bsv[ch+1] + b0.y*gsve[ch+1]*BNC + bsve[ch+1];
            o.z = a1.x*gsv[ch+2]*BNC + bsv[ch+2] + b1.x*gsve[ch+2]*BNC + bsve[ch+2];
            o.w = a1.y*gsv[ch+3]*BNC + bsv[ch+3] + b1.y*gsve[ch+3]*BNC + bsve[ch+3];
            *(float4*)(op + p*4) = o;
        }
    }
}

extern "C" void kernel_launch(void* const* d_in, const int* in_sizes, int n_in,
                              void* d_out, int out_size)
{
    (void)in_sizes; (void)n_in; (void)out_size;
    const float* x    = (const float*)d_in[0];
    const float* wq   = (const float*)d_in[1];
    const float* wk   = (const float*)d_in[2];
    const float* wv   = (const float*)d_in[3];
    const float* qrel = (const float*)d_in[4];
    const float* krel = (const float*)d_in[5];
    const float* vrel = (const float*)d_in[6];
    const float* gq = (const float*)d_in[7];   const float* bq = (const float*)d_in[8];
    const float* gk = (const float*)d_in[9];   const float* bk = (const float*)d_in[10];
    const float* gv = (const float*)d_in[11];  const float* bv = (const float*)d_in[12];
    const float* gqk= (const float*)d_in[13];  const float* bqk= (const float*)d_in[14];
    const float* gqr= (const float*)d_in[15];  const float* bqr= (const float*)d_in[16];
    const float* gkr= (const float*)d_in[17];  const float* bkr= (const float*)d_in[18];
    const float* gsv= (const float*)d_in[19];  const float* bsv= (const float*)d_in[20];
    const float* gsve=(const float*)d_in[21];  const float* bsve=(const float*)d_in[22];
    float* out = (float*)d_out;

    const int smem_bytes = (8*SPITCH + 888 + 888 + 1776) * (int)sizeof(float); // 114688
    cudaFuncSetAttribute(attn_kernel, cudaFuncAttributeMaxDynamicSharedMemorySize, smem_bytes);

    qkv_kernel<<<dim3(1568, 4), 128>>>(x, wq, wk, wv, gq, bq, gk, bk, gv, bv);
    attn_kernel<<<dim3(7, NGRP, NBATCH), 448, smem_bytes>>>(
        qrel, krel, vrel, gqk, bqk, gqr, bqr, gkr, bkr, gsv, bsv, gsve, bsve, out);
}

// round 4
// speedup vs baseline: 2.7978x; 1.8842x over previous
#include <cuda_runtime.h>
#include <cstdint>

#define NBATCH 32
#define HDIM 56
#define WDIM 56
#define CIN 128
#define OUTC 128
#define NGRP 8
#define HC 64
#define BNC 0.9995003747f   // 1/sqrt(1+1e-3)
#define SPITCH 3140         // 56*56 + 4 (ti-stride ≡ 4 mod 32 → conflict-free STS/LDS)

// Scratch buffers for q/k/v (post-BN). __device__ globals per allocation rules.
__device__ float g_qbuf[(size_t)NBATCH*HDIM*WDIM*HC];
__device__ float g_kbuf[(size_t)NBATCH*HDIM*WDIM*HC];
__device__ float g_vbuf[(size_t)NBATCH*HDIM*WDIM*OUTC];

typedef unsigned long long u64;

__device__ __forceinline__ u64 pk2(float lo, float hi){
    u64 r;
    asm("mov.b64 %0, {%1, %2};" : "=l"(r) : "r"(__float_as_uint(lo)), "r"(__float_as_uint(hi)));
    return r;
}
__device__ __forceinline__ float2 upk2(u64 v){
    unsigned lo, hi;
    asm("mov.b64 {%0, %1}, %2;" : "=r"(lo), "=r"(hi) : "l"(v));
    return make_float2(__uint_as_float(lo), __uint_as_float(hi));
}
__device__ __forceinline__ u64 ffma2(u64 a, u64 b, u64 c){
    u64 d; asm("fma.rn.f32x2 %0, %1, %2, %3;" : "=l"(d) : "l"(a), "l"(b), "l"(c)); return d;
}
__device__ __forceinline__ u64 fmul2(u64 a, u64 b){
    u64 d; asm("mul.rn.f32x2 %0, %1, %2;" : "=l"(d) : "l"(a), "l"(b)); return d;
}
__device__ __forceinline__ float hadd2(u64 v){ float2 f = upk2(v); return f.x + f.y; }

// ---------------------------------------------------------------------------
// Kernel A: fused Q/K/V 1x1-conv GEMM + BN. (unchanged)
// ---------------------------------------------------------------------------
__global__ __launch_bounds__(128) void qkv_kernel(
    const float* __restrict__ x,
    const float* __restrict__ wq, const float* __restrict__ wk, const float* __restrict__ wv,
    const float* __restrict__ gq, const float* __restrict__ bq,
    const float* __restrict__ gk, const float* __restrict__ bk,
    const float* __restrict__ gv, const float* __restrict__ bv)
{
    __shared__ float Xs[64][17];
    __shared__ float Ws[16][64];
    const int tid = threadIdx.x;
    const int tx = tid & 15;
    const int ty = tid >> 4;
    const int row0 = blockIdx.x * 64;
    const int cb = blockIdx.y;

    const float* wsrc; int wld, wcol0; float* dst; int dld, dcol0;
    const float* gam; const float* bet; int ch0;
    if (cb == 0){ wsrc=wq; wld=HC;   wcol0=0; dst=g_qbuf; dld=HC;   dcol0=0; gam=gq; bet=bq; ch0=0; }
    else if (cb == 1){ wsrc=wk; wld=HC; wcol0=0; dst=g_kbuf; dld=HC; dcol0=0; gam=gk; bet=bk; ch0=0; }
    else { int h=(cb-2)*64; wsrc=wv; wld=OUTC; wcol0=h; dst=g_vbuf; dld=OUTC; dcol0=h; gam=gv; bet=bv; ch0=h; }

    u64 acc[8][2];
    #pragma unroll
    for (int j=0;j<8;j++){ acc[j][0]=0ULL; acc[j][1]=0ULL; }

    for (int kk=0; kk<8; kk++){
        #pragma unroll
        for (int l=0;l<8;l++){
            int idx = tid + l*128;
            int r = idx >> 4, c = idx & 15;
            Xs[r][c] = x[(size_t)(row0 + r)*CIN + kk*16 + c];
        }
        #pragma unroll
        for (int l=0;l<8;l++){
            int idx = tid + l*128;
            int r = idx >> 6, c = idx & 63;
            Ws[r][c] = wsrc[(size_t)(kk*16 + r)*wld + wcol0 + c];
        }
        __syncthreads();
        #pragma unroll
        for (int k=0;k<16;k++){
            float4 b4 = *(const float4*)&Ws[k][tx*4];
            u64 b01 = pk2(b4.x, b4.y);
            u64 b23 = pk2(b4.z, b4.w);
            #pragma unroll
            for (int j=0;j<8;j++){
                float a = Xs[ty*8 + j][k];
                u64 ap = pk2(a, a);
                acc[j][0] = ffma2(ap, b01, acc[j][0]);
                acc[j][1] = ffma2(ap, b23, acc[j][1]);
            }
        }
        __syncthreads();
    }
    float sc[4], bb[4];
    #pragma unroll
    for (int c=0;c<4;c++){
        int ch = ch0 + tx*4 + c;
        sc[c] = gam[ch]*BNC;
        bb[c] = bet[ch];
    }
    #pragma unroll
    for (int j=0;j<8;j++){
        float2 f0 = upk2(acc[j][0]);
        float2 f1 = upk2(acc[j][1]);
        float4 o;
        o.x = f0.x*sc[0]+bb[0]; o.y = f0.y*sc[1]+bb[1];
        o.z = f1.x*sc[2]+bb[2]; o.w = f1.y*sc[3]+bb[3];
        *(float4*)&dst[(size_t)(row0 + ty*8 + j)*dld + dcol0 + tx*4] = o;
    }
}

// ---------------------------------------------------------------------------
// Kernel B v3: axial attention, wavefront-optimized.
// Grid (7 it, 8 g, 32 b), 448 threads, 2 blocks/SM (111 KB smem).
// Phase A: thread=(ti,w); QR/KR rows padded to 12 floats (bank-conflict-free).
// Phase C: thread=(cquad,ihalf,w), 4 i x 4 ch per thread: v loads distinct,
//          S/Inv broadcast, VR rows padded to 20 floats (conflict-free).
// Tables VR+Inv aliased onto dead QR/KR smem after phase A.
// ---------------------------------------------------------------------------
__global__ __launch_bounds__(448, 2) void attn_kernel(
    const float* __restrict__ qrel, const float* __restrict__ krel, const float* __restrict__ vrel,
    const float* __restrict__ gqk, const float* __restrict__ bqk,
    const float* __restrict__ gqr, const float* __restrict__ bqr,
    const float* __restrict__ gkr, const float* __restrict__ bkr,
    const float* __restrict__ gsv, const float* __restrict__ bsv,
    const float* __restrict__ gsve, const float* __restrict__ bsve,
    float* __restrict__ out)
{
    extern __shared__ float sm[];
    float* Ssh = sm;                   // 8*3140 = 25120 floats
    float* QRp = sm + 8*SPITCH;        // 111*12 = 1332 (phase A only)
    float* KRp = QRp + 1332;           // 1332   (phase A only)
    float* VRp = QRp;                  // 111*20 = 2220 (aliased; loaded post-A)
    float* Inv = QRp + 2220;           // 448           (aliased; written in B)

    const int it = blockIdx.x;
    const int g  = blockIdx.y;
    const int b  = blockIdx.z;
    const int tid = threadIdx.x;

    const float sqk = gqk[g]*BNC, sqr = gqr[g]*BNC, skr = gkr[g]*BNC;
    const float cbias = bqk[g] + bqr[g] + bkr[g];

    // stage QR/KR with rows padded 8 -> 12
    for (int idx = tid; idx < 888; idx += 448){
        int d = idx >> 3, c = idx & 7;
        QRp[d*12 + c] = qrel[idx];
        KRp[d*12 + c] = krel[idx];
    }
    __syncthreads();

    // ---- phase A: S[ti][j][w] ----
    {
        const int ti = tid & 7;
        const int w  = tid >> 3;
        const int i  = it*8 + ti;
        const ulonglong2* qp = (const ulonglong2*)&g_qbuf[((size_t)(b*HDIM + i)*WDIM + w)*HC + g*8];
        ulonglong2 qA = qp[0], qB = qp[1];
        const char* kbase = (const char*)&g_kbuf[((size_t)(b*HDIM)*WDIM + w)*HC + g*8];
        float* srow = &Ssh[ti*SPITCH + w];

        #pragma unroll 2
        for (int j = 0; j < 56; j++){
            const ulonglong2* kp = (const ulonglong2*)(kbase + (size_t)j*(WDIM*HC*4));
            ulonglong2 kA = kp[0], kB = kp[1];
            const ulonglong2* rp = (const ulonglong2*)&QRp[(i - j + 55)*12];
            ulonglong2 rA = rp[0], rB = rp[1];
            const ulonglong2* cp = (const ulonglong2*)&KRp[(j - i + 55)*12];
            ulonglong2 cA = cp[0], cB = cp[1];

            u64 dqk = fmul2(qA.x, kA.x); dqk = ffma2(qA.y, kA.y, dqk);
            dqk = ffma2(qB.x, kB.x, dqk); dqk = ffma2(qB.y, kB.y, dqk);
            u64 dqr = fmul2(qA.x, rA.x); dqr = ffma2(qA.y, rA.y, dqr);
            dqr = ffma2(qB.x, rB.x, dqr); dqr = ffma2(qB.y, rB.y, dqr);
            u64 dkr = fmul2(kA.x, cA.x); dkr = ffma2(kA.y, cA.y, dkr);
            dkr = ffma2(kB.x, cB.x, dkr); dkr = ffma2(kB.y, cB.y, dkr);

            srow[j*56] = hadd2(dqk)*sqk + hadd2(dqr)*sqr + hadd2(dkr)*skr + cbias;
        }
    }
    __syncthreads();

    // stage VR (rows padded 16 -> 20) into the dead QR/KR region
    for (int idx = tid; idx < 1776; idx += 448){
        int d = idx >> 4, c = idx & 15;
        VRp[d*20 + c] = vrel[idx];
    }

    // ---- phase B: softmax over w per (ti, j) row; leaves e in Ssh, 1/sum in Inv ----
    {
        const int bti = tid & 7, bj = tid >> 3;
        float4* row = (float4*)&Ssh[bti*SPITCH + bj*56];
        float m = -3.4e38f;
        #pragma unroll
        for (int p = 0; p < 14; p++){
            float4 t = row[p];
            m = fmaxf(m, fmaxf(fmaxf(t.x, t.y), fmaxf(t.z, t.w)));
        }
        float s = 0.f;
        #pragma unroll
        for (int p = 0; p < 14; p++){
            float4 t = row[p];
            t.x = __expf(t.x - m); t.y = __expf(t.y - m);
            t.z = __expf(t.z - m); t.w = __expf(t.w - m);
            s += (t.x + t.y) + (t.z + t.w);
            row[p] = t;
        }
        Inv[tid] = 1.0f / s;   // Inv[bj*8 + bti]
    }
    __syncthreads();

    // ---- phase C: sv + sve over j; 4 i x 4 ch per thread ----
    {
        const int cquad = tid & 3;
        const int ihalf = (tid >> 2) & 1;
        const int wc    = tid >> 3;
        const int ib    = it*8 + ihalf*4;

        u64 sv[4][2], se[4][2];
        #pragma unroll
        for (int p=0;p<4;p++){ sv[p][0]=0ULL; sv[p][1]=0ULL; se[p][0]=0ULL; se[p][1]=0ULL; }

        const char* vb = (const char*)&g_vbuf[((size_t)(b*HDIM)*WDIM + wc)*OUTC + g*16 + cquad*4];
        const float* S0 = &Ssh[(ihalf*4)*SPITCH + wc];

        #pragma unroll 2
        for (int j = 0; j < 56; j++){
            float4 iv = *(const float4*)&Inv[j*8 + ihalf*4];
            float p0 = S0[0*SPITCH + j*56] * iv.x;
            float p1 = S0[1*SPITCH + j*56] * iv.y;
            float p2 = S0[2*SPITCH + j*56] * iv.z;
            float p3 = S0[3*SPITCH + j*56] * iv.w;

            ulonglong2 v2 = *(const ulonglong2*)(vb + (size_t)j*(WDIM*OUTC*4));
            const int d = j - ib + 55;
            ulonglong2 e0 = *(const ulonglong2*)&VRp[(d-0)*20 + cquad*4];
            ulonglong2 e1 = *(const ulonglong2*)&VRp[(d-1)*20 + cquad*4];
            ulonglong2 e2 = *(const ulonglong2*)&VRp[(d-2)*20 + cquad*4];
            ulonglong2 e3 = *(const ulonglong2*)&VRp[(d-3)*20 + cquad*4];

            u64 P0 = pk2(p0,p0), P1 = pk2(p1,p1), P2 = pk2(p2,p2), P3 = pk2(p3,p3);
            sv[0][0]=ffma2(P0, v2.x, sv[0][0]); sv[0][1]=ffma2(P0, v2.y, sv[0][1]);
            se[0][0]=ffma2(P0, e0.x, se[0][0]); se[0][1]=ffma2(P0, e0.y, se[0][1]);
            sv[1][0]=ffma2(P1, v2.x, sv[1][0]); sv[1][1]=ffma2(P1, v2.y, sv[1][1]);
            se[1][0]=ffma2(P1, e1.x, se[1][0]); se[1][1]=ffma2(P1, e1.y, se[1][1]);
            sv[2][0]=ffma2(P2, v2.x, sv[2][0]); sv[2][1]=ffma2(P2, v2.y, sv[2][1]);
            se[2][0]=ffma2(P2, e2.x, se[2][0]); se[2][1]=ffma2(P2, e2.y, se[2][1]);
            sv[3][0]=ffma2(P3, v2.x, sv[3][0]); sv[3][1]=ffma2(P3, v2.y, sv[3][1]);
            se[3][0]=ffma2(P3, e3.x, se[3][0]); se[3][1]=ffma2(P3, e3.y, se[3][1]);
        }

        const int c0 = g*16 + cquad*4;
        float4 gv1 = *(const float4*)&gsv[c0];  float4 bv1 = *(const float4*)&bsv[c0];
        float4 gv2 = *(const float4*)&gsve[c0]; float4 bv2 = *(const float4*)&bsve[c0];
        #pragma unroll
        for (int ii = 0; ii < 4; ii++){
            float2 a0 = upk2(sv[ii][0]);
            float2 a1 = upk2(sv[ii][1]);
            float2 b0 = upk2(se[ii][0]);
            float2 b1 = upk2(se[ii][1]);
            float4 o;
            o.x = a0.x*gv1.x*BNC + bv1.x + b0.x*gv2.x*BNC + bv2.x;
            o.y = a0.y*gv1.y*BNC + bv1.y + b0.y*gv2.y*BNC + bv2.y;
            o.z = a1.x*gv1.z*BNC + bv1.z + b1.x*gv2.z*BNC + bv2.z;
            o.w = a1.y*gv1.w*BNC + bv1.w + b1.y*gv2.w*BNC + bv2.w;
            *(float4*)&out[((size_t)(b*HDIM + ib + ii)*WDIM + wc)*OUTC + c0] = o;
        }
    }
}

extern "C" void kernel_launch(void* const* d_in, const int* in_sizes, int n_in,
                              void* d_out, int out_size)
{
    (void)in_sizes; (void)n_in; (void)out_size;
    const float* x    = (const float*)d_in[0];
    const float* wq   = (const float*)d_in[1];
    const float* wk   = (const float*)d_in[2];
    const float* wv   = (const float*)d_in[3];
    const float* qrel = (const float*)d_in[4];
    const float* krel = (const float*)d_in[5];
    const float* vrel = (const float*)d_in[6];
    const float* gq = (const float*)d_in[7];   const float* bq = (const float*)d_in[8];
    const float* gk = (const float*)d_in[9];   const float* bk = (const float*)d_in[10];
    const float* gv = (const float*)d_in[11];  const float* bv = (const float*)d_in[12];
    const float* gqk= (const float*)d_in[13];  const float* bqk= (const float*)d_in[14];
    const float* gqr= (const float*)d_in[15];  const float* bqr= (const float*)d_in[16];
    const float* gkr= (const float*)d_in[17];  const float* bkr= (const float*)d_in[18];
    const float* gsv= (const float*)d_in[19];  const float* bsv= (const float*)d_in[20];
    const float* gsve=(const float*)d_in[21];  const float* bsve=(const float*)d_in[22];
    float* out = (float*)d_out;

    const int smem_bytes = (8*SPITCH + 2220 + 448) * (int)sizeof(float); // 111152
    cudaFuncSetAttribute(attn_kernel, cudaFuncAttributeMaxDynamicSharedMemorySize, smem_bytes);

    qkv_kernel<<<dim3(1568, 4), 128>>>(x, wq, wk, wv, gq, bq, gk, bk, gv, bv);
    attn_kernel<<<dim3(7, NGRP, NBATCH), 448, smem_bytes>>>(
        qrel, krel, vrel, gqk, bqk, gqr, bqr, gkr, bkr, gsv, bsv, gsve, bsve, out);
}

// round 7
// speedup vs baseline: 2.9120x; 1.0408x over previous
#include <cuda_runtime.h>
#include <cstdint>

#define NBATCH 32
#define HDIM 56
#define WDIM 56
#define CIN 128
#define OUTC 128
#define NGRP 8
#define HC 64
#define BNC 0.9995003747f   // 1/sqrt(1+1e-3)
#define SPITCH 3140         // 56*56 + 4 (ti-stride ≡ 4 mod 32 → conflict-free STS/LDS)
#define HW 3136             // 56*56

// Scratch buffers (our layouts, g-major for dense attention access):
//  q: [b][g][hw][8]   k: [b][g][hw][8]   v: [b][g][hw][16]
__device__ float g_qbuf[(size_t)NBATCH*NGRP*HW*8];
__device__ float g_kbuf[(size_t)NBATCH*NGRP*HW*8];
__device__ float g_vbuf[(size_t)NBATCH*NGRP*HW*16];

typedef unsigned long long u64;

__device__ __forceinline__ u64 pk2(float lo, float hi){
    u64 r;
    asm("mov.b64 %0, {%1, %2};" : "=l"(r) : "r"(__float_as_uint(lo)), "r"(__float_as_uint(hi)));
    return r;
}
__device__ __forceinline__ float2 upk2(u64 v){
    unsigned lo, hi;
    asm("mov.b64 {%0, %1}, %2;" : "=r"(lo), "=r"(hi) : "l"(v));
    return make_float2(__uint_as_float(lo), __uint_as_float(hi));
}
__device__ __forceinline__ u64 ffma2(u64 a, u64 b, u64 c){
    u64 d; asm("fma.rn.f32x2 %0, %1, %2, %3;" : "=l"(d) : "l"(a), "l"(b), "l"(c)); return d;
}
__device__ __forceinline__ u64 fmul2(u64 a, u64 b){
    u64 d; asm("mul.rn.f32x2 %0, %1, %2;" : "=l"(d) : "l"(a), "l"(b)); return d;
}
__device__ __forceinline__ float hadd2(u64 v){ float2 f = upk2(v); return f.x + f.y; }

// ---------------------------------------------------------------------------
// Kernel A: fused Q/K/V 1x1-conv GEMM + BN, g-major output layout.
// 64-row x 64-col tile, 128 threads. XsT transpose (pitch 68: 16B-aligned
// rows — pitch 65 was the round-5 misaligned-address bug) for LDS.128 inner
// loop. Epilogue bounces the tile through Ts so STG into the g-major layout
// is coalesced. 3136 % 64 == 0, so each tile's 64 rows stay within one b.
// ---------------------------------------------------------------------------
__global__ __launch_bounds__(128) void qkv_kernel(
    const float* __restrict__ x,
    const float* __restrict__ wq, const float* __restrict__ wk, const float* __restrict__ wv,
    const float* __restrict__ gq, const float* __restrict__ bq,
    const float* __restrict__ gk, const float* __restrict__ bk,
    const float* __restrict__ gv, const float* __restrict__ bv)
{
    __shared__ float XsT[16][68];   // [k][row], pitch 68 (16B-aligned rows)
    __shared__ float Ws[16][64];
    __shared__ float Ts[64][68];    // bounce tile, pitch 68
    const int tid = threadIdx.x;
    const int tx = tid & 15;
    const int ty = tid >> 4;
    const int row0 = blockIdx.x * 64;
    const int cb = blockIdx.y;
    const int bb = row0 / HW;
    const int hw0 = row0 - bb*HW;

    const float* wsrc; int wld, wcol0; int ch0;
    const float* gam; const float* bet;
    if (cb == 0){ wsrc=wq; wld=HC;  wcol0=0;  gam=gq; bet=bq; ch0=0; }
    else if (cb == 1){ wsrc=wk; wld=HC; wcol0=0; gam=gk; bet=bk; ch0=0; }
    else { int h=(cb-2)*64; wsrc=wv; wld=OUTC; wcol0=h; gam=gv; bet=bv; ch0=h; }

    u64 acc[8][2];
    #pragma unroll
    for (int j=0;j<8;j++){ acc[j][0]=0ULL; acc[j][1]=0ULL; }

    for (int kk=0; kk<8; kk++){
        #pragma unroll
        for (int l=0;l<8;l++){
            int idx = tid + l*128;
            int r = idx >> 4, c = idx & 15;
            XsT[c][r] = x[(size_t)(row0 + r)*CIN + kk*16 + c];
        }
        #pragma unroll
        for (int l=0;l<8;l++){
            int idx = tid + l*128;
            int r = idx >> 6, c = idx & 63;
            Ws[r][c] = wsrc[(size_t)(kk*16 + r)*wld + wcol0 + c];
        }
        __syncthreads();
        #pragma unroll
        for (int k=0;k<16;k++){
            float4 b4 = *(const float4*)&Ws[k][tx*4];
            u64 b01 = pk2(b4.x, b4.y);
            u64 b23 = pk2(b4.z, b4.w);
            float4 a0 = *(const float4*)&XsT[k][ty*8];
            float4 a1 = *(const float4*)&XsT[k][ty*8 + 4];
            float av[8] = {a0.x,a0.y,a0.z,a0.w,a1.x,a1.y,a1.z,a1.w};
            #pragma unroll
            for (int j=0;j<8;j++){
                u64 ap = pk2(av[j], av[j]);
                acc[j][0] = ffma2(ap, b01, acc[j][0]);
                acc[j][1] = ffma2(ap, b23, acc[j][1]);
            }
        }
        __syncthreads();
    }

    // BN + write to bounce tile
    float sc[4], bo[4];
    #pragma unroll
    for (int c=0;c<4;c++){
        int ch = ch0 + tx*4 + c;
        sc[c] = gam[ch]*BNC;
        bo[c] = bet[ch];
    }
    #pragma unroll
    for (int j=0;j<8;j++){
        float2 f0 = upk2(acc[j][0]);
        float2 f1 = upk2(acc[j][1]);
        float4 o;
        o.x = f0.x*sc[0]+bo[0]; o.y = f0.y*sc[1]+bo[1];
        o.z = f1.x*sc[2]+bo[2]; o.w = f1.y*sc[3]+bo[3];
        *(float4*)&Ts[ty*8 + j][tx*4] = o;
    }
    __syncthreads();

    // coalesced store into g-major layout
    if (cb < 2){
        float* dst = (cb == 0) ? g_qbuf : g_kbuf;
        // 8 g-slices x 64 rows x 2 halves : t over 1024 float4
        #pragma unroll
        for (int p = 0; p < 8; p++){
            int t = tid + p*128;
            int g = t >> 7;
            int r = (t >> 1) & 63;
            int half = t & 1;
            float4 val = *(const float4*)&Ts[r][g*8 + half*4];
            size_t o = (((size_t)bb*NGRP + g)*HW + hw0 + r)*8 + half*4;
            *(float4*)&dst[o] = val;
        }
    } else {
        // 4 g-slices (16c each) x 64 rows x 4 quads : t over 1024 float4
        #pragma unroll
        for (int p = 0; p < 8; p++){
            int t = tid + p*128;
            int gl = t >> 8;
            int r = (t >> 2) & 63;
            int q4 = t & 3;
            int g = (cb-2)*4 + gl;
            float4 val = *(const float4*)&Ts[r][gl*16 + q4*4];
            size_t o = (((size_t)bb*NGRP + g)*HW + hw0 + r)*16 + q4*4;
            *(float4*)&g_vbuf[o] = val;
        }
    }
}

// ---------------------------------------------------------------------------
// Kernel B v4: axial attention on g-major scratch layouts.
// Grid (7 it, 8 g, 32 b), 448 threads, 2 blocks/SM (111 KB smem).
// Phase A: thread=(ti,w); k row loads 128B-contiguous per warp (1 wf/LDG).
// Phase C: thread=(cquad,ihalf,w); v loads 256B-contiguous per warp (2 wf/j).
// ---------------------------------------------------------------------------
__global__ __launch_bounds__(448, 2) void attn_kernel(
    const float* __restrict__ qrel, const float* __restrict__ krel, const float* __restrict__ vrel,
    const float* __restrict__ gqk, const float* __restrict__ bqk,
    const float* __restrict__ gqr, const float* __restrict__ bqr,
    const float* __restrict__ gkr, const float* __restrict__ bkr,
    const float* __restrict__ gsv, const float* __restrict__ bsv,
    const float* __restrict__ gsve, const float* __restrict__ bsve,
    float* __restrict__ out)
{
    extern __shared__ float sm[];
    float* Ssh = sm;                   // 8*3140 = 25120 floats
    float* QRp = sm + 8*SPITCH;        // 111*12 = 1332 (phase A only)
    float* KRp = QRp + 1332;           // 1332   (phase A only)
    float* VRp = QRp;                  // 111*20 = 2220 (aliased; loaded post-A)
    float* Inv = QRp + 2220;           // 448           (aliased; written in B)

    const int it = blockIdx.x;
    const int g  = blockIdx.y;
    const int b  = blockIdx.z;
    const int tid = threadIdx.x;

    const float sqk = gqk[g]*BNC, sqr = gqr[g]*BNC, skr = gkr[g]*BNC;
    const float cbias = bqk[g] + bqr[g] + bkr[g];
    const size_t slice = ((size_t)b*NGRP + g)*HW;

    // stage QR/KR with rows padded 8 -> 12
    for (int idx = tid; idx < 888; idx += 448){
        int d = idx >> 3, c = idx & 7;
        QRp[d*12 + c] = qrel[idx];
        KRp[d*12 + c] = krel[idx];
    }
    __syncthreads();

    // ---- phase A: S[ti][j][w] ----
    {
        const int ti = tid & 7;
        const int w  = tid >> 3;
        const int i  = it*8 + ti;
        const ulonglong2* qp = (const ulonglong2*)&g_qbuf[(slice + i*56 + w)*8];
        ulonglong2 qA = qp[0], qB = qp[1];
        const char* kbase = (const char*)&g_kbuf[(slice + w)*8];   // j stride 1792B
        float* srow = &Ssh[ti*SPITCH + w];

        #pragma unroll 2
        for (int j = 0; j < 56; j++){
            const ulonglong2* kp = (const ulonglong2*)(kbase + (size_t)j*1792);
            ulonglong2 kA = kp[0], kB = kp[1];
            const ulonglong2* rp = (const ulonglong2*)&QRp[(i - j + 55)*12];
            ulonglong2 rA = rp[0], rB = rp[1];
            const ulonglong2* cp = (const ulonglong2*)&KRp[(j - i + 55)*12];
            ulonglong2 cA = cp[0], cB = cp[1];

            u64 dqk = fmul2(qA.x, kA.x); dqk = ffma2(qA.y, kA.y, dqk);
            dqk = ffma2(qB.x, kB.x, dqk); dqk = ffma2(qB.y, kB.y, dqk);
            u64 dqr = fmul2(qA.x, rA.x); dqr = ffma2(qA.y, rA.y, dqr);
            dqr = ffma2(qB.x, rB.x, dqr); dqr = ffma2(qB.y, rB.y, dqr);
            u64 dkr = fmul2(kA.x, cA.x); dkr = ffma2(kA.y, cA.y, dkr);
            dkr = ffma2(kB.x, cB.x, dkr); dkr = ffma2(kB.y, cB.y, dkr);

            srow[j*56] = hadd2(dqk)*sqk + hadd2(dqr)*sqr + hadd2(dkr)*skr + cbias;
        }
    }
    __syncthreads();

    // stage VR (rows padded 16 -> 20) into the dead QR/KR region
    for (int idx = tid; idx < 1776; idx += 448){
        int d = idx >> 4, c = idx & 15;
        VRp[d*20 + c] = vrel[idx];
    }

    // ---- phase B: softmax over w per (ti, j) row; e in Ssh, 1/sum in Inv ----
    {
        const int bti = tid & 7, bj = tid >> 3;
        float4* row = (float4*)&Ssh[bti*SPITCH + bj*56];
        float m = -3.4e38f;
        #pragma unroll
        for (int p = 0; p < 14; p++){
            float4 t = row[p];
            m = fmaxf(m, fmaxf(fmaxf(t.x, t.y), fmaxf(t.z, t.w)));
        }
        float s = 0.f;
        #pragma unroll
        for (int p = 0; p < 14; p++){
            float4 t = row[p];
            t.x = __expf(t.x - m); t.y = __expf(t.y - m);
            t.z = __expf(t.z - m); t.w = __expf(t.w - m);
            s += (t.x + t.y) + (t.z + t.w);
            row[p] = t;
        }
        Inv[tid] = 1.0f / s;   // Inv[bj*8 + bti]
    }
    __syncthreads();

    // ---- phase C: sv + sve over j; 4 i x 4 ch per thread ----
    {
        const int cquad = tid & 3;
        const int ihalf = (tid >> 2) & 1;
        const int wc    = tid >> 3;
        const int ib    = it*8 + ihalf*4;

        u64 sv[4][2], se[4][2];
        #pragma unroll
        for (int p=0;p<4;p++){ sv[p][0]=0ULL; sv[p][1]=0ULL; se[p][0]=0ULL; se[p][1]=0ULL; }

        const char* vb = (const char*)&g_vbuf[(slice + wc)*16 + cquad*4];   // j stride 3584B
        const float* S0 = &Ssh[(ihalf*4)*SPITCH + wc];

        #pragma unroll 2
        for (int j = 0; j < 56; j++){
            float4 iv = *(const float4*)&Inv[j*8 + ihalf*4];
            float p0 = S0[0*SPITCH + j*56] * iv.x;
            float p1 = S0[1*SPITCH + j*56] * iv.y;
            float p2 = S0[2*SPITCH + j*56] * iv.z;
            float p3 = S0[3*SPITCH + j*56] * iv.w;

            ulonglong2 v2 = *(const ulonglong2*)(vb + (size_t)j*3584);
            const int d = j - ib + 55;
            ulonglong2 e0 = *(const ulonglong2*)&VRp[(d-0)*20 + cquad*4];
            ulonglong2 e1 = *(const ulonglong2*)&VRp[(d-1)*20 + cquad*4];
            ulonglong2 e2 = *(const ulonglong2*)&VRp[(d-2)*20 + cquad*4];
            ulonglong2 e3 = *(const ulonglong2*)&VRp[(d-3)*20 + cquad*4];

            u64 P0 = pk2(p0,p0), P1 = pk2(p1,p1), P2 = pk2(p2,p2), P3 = pk2(p3,p3);
            sv[0][0]=ffma2(P0, v2.x, sv[0][0]); sv[0][1]=ffma2(P0, v2.y, sv[0][1]);
            se[0][0]=ffma2(P0, e0.x, se[0][0]); se[0][1]=ffma2(P0, e0.y, se[0][1]);
            sv[1][0]=ffma2(P1, v2.x, sv[1][0]); sv[1][1]=ffma2(P1, v2.y, sv[1][1]);
            se[1][0]=ffma2(P1, e1.x, se[1][0]); se[1][1]=ffma2(P1, e1.y, se[1][1]);
            sv[2][0]=ffma2(P2, v2.x, sv[2][0]); sv[2][1]=ffma2(P2, v2.y, sv[2][1]);
            se[2][0]=ffma2(P2, e2.x, se[2][0]); se[2][1]=ffma2(P2, e2.y, se[2][1]);
            sv[3][0]=ffma2(P3, v2.x, sv[3][0]); sv[3][1]=ffma2(P3, v2.y, sv[3][1]);
            se[3][0]=ffma2(P3, e3.x, se[3][0]); se[3][1]=ffma2(P3, e3.y, se[3][1]);
        }

        const int c0 = g*16 + cquad*4;
        float4 gv1 = *(const float4*)&gsv[c0];  float4 bv1 = *(const float4*)&bsv[c0];
        float4 gv2 = *(const float4*)&gsve[c0]; float4 bv2 = *(const float4*)&bsve[c0];
        #pragma unroll
        for (int ii = 0; ii < 4; ii++){
            float2 a0 = upk2(sv[ii][0]);
            float2 a1 = upk2(sv[ii][1]);
            float2 b0 = upk2(se[ii][0]);
            float2 b1 = upk2(se[ii][1]);
            float4 o;
            o.x = a0.x*gv1.x*BNC + bv1.x + b0.x*gv2.x*BNC + bv2.x;
            o.y = a0.y*gv1.y*BNC + bv1.y + b0.y*gv2.y*BNC + bv2.y;
            o.z = a1.x*gv1.z*BNC + bv1.z + b1.x*gv2.z*BNC + bv2.z;
            o.w = a1.y*gv1.w*BNC + bv1.w + b1.y*gv2.w*BNC + bv2.w;
            *(float4*)&out[((size_t)(b*HDIM + ib + ii)*WDIM + wc)*OUTC + c0] = o;
        }
    }
}

extern "C" void kernel_launch(void* const* d_in, const int* in_sizes, int n_in,
                              void* d_out, int out_size)
{
    (void)in_sizes; (void)n_in; (void)out_size;
    const float* x    = (const float*)d_in[0];
    const float* wq   = (const float*)d_in[1];
    const float* wk   = (const float*)d_in[2];
    const float* wv   = (const float*)d_in[3];
    const float* qrel = (const float*)d_in[4];
    const float* krel = (const float*)d_in[5];
    const float* vrel = (const float*)d_in[6];
    const float* gq = (const float*)d_in[7];   const float* bq = (const float*)d_in[8];
    const float* gk = (const float*)d_in[9];   const float* bk = (const float*)d_in[10];
    const float* gv = (const float*)d_in[11];  const float* bv = (const float*)d_in[12];
    const float* gqk= (const float*)d_in[13];  const float* bqk= (const float*)d_in[14];
    const float* gqr= (const float*)d_in[15];  const float* bqr= (const float*)d_in[16];
    const float* gkr= (const float*)d_in[17];  const float* bkr= (const float*)d_in[18];
    const float* gsv= (const float*)d_in[19];  const float* bsv= (const float*)d_in[20];
    const float* gsve=(const float*)d_in[21];  const float* bsve=(const float*)d_in[22];
    float* out = (float*)d_out;

    const int smem_bytes = (8*SPITCH + 2220 + 448) * (int)sizeof(float); // 111152
    cudaFuncSetAttribute(attn_kernel, cudaFuncAttributeMaxDynamicSharedMemorySize, smem_bytes);

    qkv_kernel<<<dim3(1568, 4), 128>>>(x, wq, wk, wv, gq, bq, gk, bk, gv, bv);
    attn_kernel<<<dim3(7, NGRP, NBATCH), 448, smem_bytes>>>(
        qrel, krel, vrel, gqk, bqk, gqr, bqr, gkr, bkr, gsv, bsv, gsve, bsve, out);
}